// round 15
// baseline (speedup 1.0000x reference)
#include <cuda_runtime.h>
#include <cuda_bf16.h>
#include <cstdint>

#define MAX_NODES 100000
#define CAP 192          // max in-degree slots (Poisson(64): P(>=192) < 1e-40)
#define CNT_STRIDE 8     // one counter per 32B sector (proven best)
#define F_IN 4
#define F_HID 16
#define F_OUT 2

// Scratch (__device__ globals; no runtime allocation).
// g_cnt starts zero (bss) and is re-zeroed by k_agg2 every call — no memset needed.
__device__ int    g_cnt[MAX_NODES * CNT_STRIDE];         // padded in-degree counters
__device__ __align__(16) int g_bucket[MAX_NODES * CAP];  // per-dst src lists
__device__ float  g_dinv[MAX_NODES];
__device__ __align__(16) float4 g_xs4[MAX_NODES + 1];    // x * dinv; [N] = 0 sentinel
__device__ __align__(8)  float2 g_t2s[MAX_NODES + 1];    // t2 * dinv; [N] = 0 sentinel

__device__ __forceinline__ int4 ldcs_int4(const int* p) {
    int4 v;
    asm volatile("ld.global.cs.v4.s32 {%0, %1, %2, %3}, [%4];"
                 : "=r"(v.x), "=r"(v.y), "=r"(v.z), "=r"(v.w) : "l"(p));
    return v;
}

// ---------------------------------------------------------------------------
// placement: build per-dst src lists; padded counter doubles as degree.
// 8 edges/thread; streaming edge loads; unconditional clamped stores.
// NO PDL on this kernel (races with prior replay's agg2 counter reset).
// ---------------------------------------------------------------------------
__global__ void __launch_bounds__(512)
k_place(const int* __restrict__ src, const int* __restrict__ dst, int E) {
    int e0 = (blockIdx.x * blockDim.x + threadIdx.x) * 8;
    if (e0 + 7 < E) {
        int4 sa = ldcs_int4(src + e0);
        int4 sb = ldcs_int4(src + e0 + 4);
        int4 da = ldcs_int4(dst + e0);
        int4 db = ldcs_int4(dst + e0 + 4);
        int p;
        p = atomicAdd(&g_cnt[da.x * CNT_STRIDE], 1); g_bucket[da.x * CAP + min(p, CAP - 1)] = sa.x;
        p = atomicAdd(&g_cnt[da.y * CNT_STRIDE], 1); g_bucket[da.y * CAP + min(p, CAP - 1)] = sa.y;
        p = atomicAdd(&g_cnt[da.z * CNT_STRIDE], 1); g_bucket[da.z * CAP + min(p, CAP - 1)] = sa.z;
        p = atomicAdd(&g_cnt[da.w * CNT_STRIDE], 1); g_bucket[da.w * CAP + min(p, CAP - 1)] = sa.w;
        p = atomicAdd(&g_cnt[db.x * CNT_STRIDE], 1); g_bucket[db.x * CAP + min(p, CAP - 1)] = sb.x;
        p = atomicAdd(&g_cnt[db.y * CNT_STRIDE], 1); g_bucket[db.y * CAP + min(p, CAP - 1)] = sb.y;
        p = atomicAdd(&g_cnt[db.z * CNT_STRIDE], 1); g_bucket[db.z * CAP + min(p, CAP - 1)] = sb.z;
        p = atomicAdd(&g_cnt[db.w * CNT_STRIDE], 1); g_bucket[db.w * CAP + min(p, CAP - 1)] = sb.w;
    } else {
        for (int e = e0; e < E; e++) {
            int s = src[e], d = dst[e];
            int p = atomicAdd(&g_cnt[d * CNT_STRIDE], 1);
            g_bucket[d * CAP + min(p, CAP - 1)] = s;
        }
    }
}

// ---------------------------------------------------------------------------
// prep: deg = cnt + 1 (self loop); dinv = rsqrt(deg); xs = x * dinv;
// pad bucket row to multiple of 4 with sentinel index n (zero row).
// PDL secondary: wait for place before reading g_cnt/g_bucket.
// ---------------------------------------------------------------------------
__global__ void k_prep(const float* __restrict__ x, int n) {
    cudaGridDependencySynchronize();
    int i = blockIdx.x * blockDim.x + threadIdx.x;
    if (i == 0) {
        g_xs4[n] = make_float4(0.f, 0.f, 0.f, 0.f);
        g_t2s[n] = make_float2(0.f, 0.f);
    }
    if (i >= n) return;
    int cnt = g_cnt[i * CNT_STRIDE]; if (cnt > CAP) cnt = CAP;
    // sentinel-pad to multiple of 4 so agg gathers need no tail guards
    int padded = (cnt + 3) & ~3;
    for (int k = cnt; k < padded; k++) g_bucket[i * CAP + k] = n;

    float dv = rsqrtf((float)(cnt + 1));
    g_dinv[i] = dv;
    float4 xv = reinterpret_cast<const float4*>(x)[i];
    g_xs4[i] = make_float4(xv.x * dv, xv.y * dv, xv.z * dv, xv.w * dv);
}

// ---------------------------------------------------------------------------
// agg1 + dense: HALF-WARP per node (two nodes per warp), unguarded int4 gathers.
//   a = dinv * (Σ_nbrs xs[s] + xs[node]);  h = relu(a@W1+b1);  t2s = (h@W2)*dinv
// PDL secondary: wait for prep.
// ---------------------------------------------------------------------------
__global__ void __launch_bounds__(256)
k_agg1(const float* __restrict__ W1, const float* __restrict__ b1,
       const float* __restrict__ W2, int n) {
    cudaGridDependencySynchronize();
    int warp = (blockIdx.x * blockDim.x + threadIdx.x) >> 5;
    int lane = threadIdx.x & 31;
    int half = lane >> 4;            // 0 or 1
    int hlane = lane & 15;
    int node = warp * 2 + half;
    if (node >= n) return;

    int deg = g_cnt[node * CNT_STRIDE]; if (deg > CAP) deg = CAP;
    int nq = (deg + 3) >> 2;         // int4 groups (sentinel-padded)
    const int4* list = reinterpret_cast<const int4*>(&g_bucket[node * CAP]);

    float4 acc = make_float4(0.f, 0.f, 0.f, 0.f);
    for (int q = hlane; q < nq; q += 16) {
        int4 s4 = __ldg(list + q);
        float4 v0 = __ldg(&g_xs4[s4.x]);
        float4 v1 = __ldg(&g_xs4[s4.y]);
        float4 v2 = __ldg(&g_xs4[s4.z]);
        float4 v3 = __ldg(&g_xs4[s4.w]);
        acc.x += (v0.x + v1.x) + (v2.x + v3.x);
        acc.y += (v0.y + v1.y) + (v2.y + v3.y);
        acc.z += (v0.z + v1.z) + (v2.z + v3.z);
        acc.w += (v0.w + v1.w) + (v2.w + v3.w);
    }
#pragma unroll
    for (int off = 8; off; off >>= 1) {
        acc.x += __shfl_xor_sync(0xffffffffu, acc.x, off);
        acc.y += __shfl_xor_sync(0xffffffffu, acc.y, off);
        acc.z += __shfl_xor_sync(0xffffffffu, acc.z, off);
        acc.w += __shfl_xor_sync(0xffffffffu, acc.w, off);
    }
    float dv = g_dinv[node];
    float4 self = __ldg(&g_xs4[node]);
    float4 a = make_float4((acc.x + self.x) * dv, (acc.y + self.y) * dv,
                           (acc.z + self.z) * dv, (acc.w + self.w) * dv);

    // MLP: the 16 lanes of each half-warp own the 16 hidden units of its node
    int j = hlane;
    float h = __ldg(&b1[j]);
    h = fmaf(a.x, __ldg(&W1[0 * F_HID + j]), h);
    h = fmaf(a.y, __ldg(&W1[1 * F_HID + j]), h);
    h = fmaf(a.z, __ldg(&W1[2 * F_HID + j]), h);
    h = fmaf(a.w, __ldg(&W1[3 * F_HID + j]), h);
    h = fmaxf(h, 0.0f);
    float p0 = h * __ldg(&W2[j * F_OUT + 0]);
    float p1 = h * __ldg(&W2[j * F_OUT + 1]);
#pragma unroll
    for (int off = 8; off; off >>= 1) {
        p0 += __shfl_xor_sync(0xffffffffu, p0, off);
        p1 += __shfl_xor_sync(0xffffffffu, p1, off);
    }
    if (hlane == 0) g_t2s[node] = make_float2(p0 * dv, p1 * dv);
}

// ---------------------------------------------------------------------------
// agg2 + bias: HALF-WARP per node, unguarded int4 gathers.
//   out = b2 + dinv * (Σ_nbrs t2s[s] + t2s[node])
// Self-zeros this node's counter for the next graph replay (last reader).
// PDL secondary: wait for agg1.
// ---------------------------------------------------------------------------
__global__ void __launch_bounds__(256)
k_agg2(const float* __restrict__ b2, float* __restrict__ out, int n) {
    cudaGridDependencySynchronize();
    int warp = (blockIdx.x * blockDim.x + threadIdx.x) >> 5;
    int lane = threadIdx.x & 31;
    int half = lane >> 4;
    int hlane = lane & 15;
    int node = warp * 2 + half;
    if (node >= n) return;

    int deg = g_cnt[node * CNT_STRIDE]; if (deg > CAP) deg = CAP;
    int nq = (deg + 3) >> 2;
    const int4* list = reinterpret_cast<const int4*>(&g_bucket[node * CAP]);

    float a0 = 0.f, a1 = 0.f;
    for (int q = hlane; q < nq; q += 16) {
        int4 s4 = __ldg(list + q);
        float2 v0 = __ldg(&g_t2s[s4.x]);
        float2 v1 = __ldg(&g_t2s[s4.y]);
        float2 v2 = __ldg(&g_t2s[s4.z]);
        float2 v3 = __ldg(&g_t2s[s4.w]);
        a0 += (v0.x + v1.x) + (v2.x + v3.x);
        a1 += (v0.y + v1.y) + (v2.y + v3.y);
    }
#pragma unroll
    for (int off = 8; off; off >>= 1) {
        a0 += __shfl_xor_sync(0xffffffffu, a0, off);
        a1 += __shfl_xor_sync(0xffffffffu, a1, off);
    }
    if (hlane == 0) {
        float dv = g_dinv[node];
        float2 self = g_t2s[node];
        float2 o;
        o.x = fmaf(dv, a0 + self.x, __ldg(&b2[0]));
        o.y = fmaf(dv, a1 + self.y, __ldg(&b2[1]));
        reinterpret_cast<float2*>(out)[node] = o;
        g_cnt[node * CNT_STRIDE] = 0;   // reset for next call (replaces memset node)
    }
}

// ---------------------------------------------------------------------------
// Launch — prep/agg1/agg2 use PDL (overlap launch with predecessor's drain);
// place stays fully stream-serialized (it conflicts with prior replay's agg2).
// ---------------------------------------------------------------------------
template <typename... Args>
static void launch_pdl(void (*kern)(Args...), int grid, int block, Args... args) {
    cudaLaunchConfig_t cfg = {};
    cfg.gridDim = dim3(grid);
    cfg.blockDim = dim3(block);
    cudaLaunchAttribute attr[1];
    attr[0].id = cudaLaunchAttributeProgrammaticStreamSerialization;
    attr[0].val.programmaticStreamSerializationAllowed = 1;
    cfg.attrs = attr;
    cfg.numAttrs = 1;
    cudaLaunchKernelEx(&cfg, kern, args...);
}

extern "C" void kernel_launch(void* const* d_in, const int* in_sizes, int n_in,
                              void* d_out, int out_size) {
    const float* x  = (const float*)d_in[0];
    const int*   ei = (const int*)d_in[1];   // int32 indices
    const float* W1 = (const float*)d_in[2];
    const float* b1 = (const float*)d_in[3];
    const float* W2 = (const float*)d_in[4];
    const float* b2 = (const float*)d_in[5];
    float* out = (float*)d_out;

    int N = in_sizes[0] / F_IN;
    int E = in_sizes[1] / 2;

    const int* src = ei;
    const int* dst = ei + E;

    const int T = 256;
    const int TP = 512;                       // place block size
    int nblk = (N + T - 1) / T;
    int e8 = (E + 7) / 8;
    int eblk = (e8 + TP - 1) / TP;
    int npairs = (N + 1) / 2;                 // two nodes per warp
    int wblk = (npairs + 7) / 8;              // 8 warps per CTA

    k_place<<<eblk, TP>>>(src, dst, E);
    launch_pdl(k_prep, nblk, T, x, N);
    launch_pdl(k_agg1, wblk, T, W1, b1, W2, N);
    launch_pdl(k_agg2, wblk, T, b2, out, N);
}

// round 16
// speedup vs baseline: 1.0153x; 1.0153x over previous
#include <cuda_runtime.h>
#include <cuda_bf16.h>
#include <cstdint>

#define MAX_NODES 100000
#define CAP 192          // max in-degree slots (Poisson(64): P(>=192) < 1e-40)
#define CNT_STRIDE 8     // one counter per 32B sector (proven best)
#define F_IN 4
#define F_HID 16
#define F_OUT 2

// Scratch (__device__ globals; no runtime allocation).
// g_cnt starts zero (bss) and is re-zeroed by k_agg2 every call — no memset needed.
__device__ int    g_cnt[MAX_NODES * CNT_STRIDE];         // padded in-degree counters
__device__ __align__(16) int g_bucket[MAX_NODES * CAP];  // per-dst src lists
__device__ float  g_dinv[MAX_NODES];
__device__ __align__(16) float4 g_xs4[MAX_NODES + 1];    // x * dinv; [N] = 0 sentinel
__device__ __align__(8)  float2 g_t2s[MAX_NODES + 1];    // t2 * dinv; [N] = 0 sentinel

// ---------------------------------------------------------------------------
// placement: build per-dst src lists; padded counter doubles as degree.
// 8 edges/thread. NO PDL on this kernel (races with prior replay's agg2 reset).
// ---------------------------------------------------------------------------
__global__ void __launch_bounds__(512)
k_place(const int* __restrict__ src, const int* __restrict__ dst, int E) {
    int e0 = (blockIdx.x * blockDim.x + threadIdx.x) * 8;
    if (e0 + 7 < E) {
        int4 sa = *reinterpret_cast<const int4*>(src + e0);
        int4 sb = *reinterpret_cast<const int4*>(src + e0 + 4);
        int4 da = *reinterpret_cast<const int4*>(dst + e0);
        int4 db = *reinterpret_cast<const int4*>(dst + e0 + 4);
        int p;
        p = atomicAdd(&g_cnt[da.x * CNT_STRIDE], 1); if (p < CAP) g_bucket[da.x * CAP + p] = sa.x;
        p = atomicAdd(&g_cnt[da.y * CNT_STRIDE], 1); if (p < CAP) g_bucket[da.y * CAP + p] = sa.y;
        p = atomicAdd(&g_cnt[da.z * CNT_STRIDE], 1); if (p < CAP) g_bucket[da.z * CAP + p] = sa.z;
        p = atomicAdd(&g_cnt[da.w * CNT_STRIDE], 1); if (p < CAP) g_bucket[da.w * CAP + p] = sa.w;
        p = atomicAdd(&g_cnt[db.x * CNT_STRIDE], 1); if (p < CAP) g_bucket[db.x * CAP + p] = sb.x;
        p = atomicAdd(&g_cnt[db.y * CNT_STRIDE], 1); if (p < CAP) g_bucket[db.y * CAP + p] = sb.y;
        p = atomicAdd(&g_cnt[db.z * CNT_STRIDE], 1); if (p < CAP) g_bucket[db.z * CAP + p] = sb.z;
        p = atomicAdd(&g_cnt[db.w * CNT_STRIDE], 1); if (p < CAP) g_bucket[db.w * CAP + p] = sb.w;
    } else {
        for (int e = e0; e < E; e++) {
            int s = src[e], d = dst[e];
            int p = atomicAdd(&g_cnt[d * CNT_STRIDE], 1);
            if (p < CAP) g_bucket[d * CAP + p] = s;
        }
    }
}

// ---------------------------------------------------------------------------
// prep: deg = cnt + 1 (self loop); dinv = rsqrt(deg); xs = x * dinv;
// pad bucket row to multiple of 4 with sentinel index n (zero row).
// PDL secondary: wait for place before reading g_cnt/g_bucket.
// ---------------------------------------------------------------------------
__global__ void k_prep(const float* __restrict__ x, int n) {
    cudaGridDependencySynchronize();
    int i = blockIdx.x * blockDim.x + threadIdx.x;
    if (i == 0) {
        g_xs4[n] = make_float4(0.f, 0.f, 0.f, 0.f);
        g_t2s[n] = make_float2(0.f, 0.f);
    }
    if (i >= n) return;
    int cnt = g_cnt[i * CNT_STRIDE]; if (cnt > CAP) cnt = CAP;
    // sentinel-pad to multiple of 4 so agg gathers need no tail guards
    int padded = (cnt + 3) & ~3;
    for (int k = cnt; k < padded; k++) g_bucket[i * CAP + k] = n;

    float dv = rsqrtf((float)(cnt + 1));
    g_dinv[i] = dv;
    float4 xv = reinterpret_cast<const float4*>(x)[i];
    g_xs4[i] = make_float4(xv.x * dv, xv.y * dv, xv.z * dv, xv.w * dv);
}

// ---------------------------------------------------------------------------
// agg1 + dense: HALF-WARP per node (two nodes per warp), unguarded int4 gathers.
//   a = dinv * (Σ_nbrs xs[s] + xs[node]);  h = relu(a@W1+b1);  t2s = (h@W2)*dinv
// PDL secondary: wait for prep.
// ---------------------------------------------------------------------------
__global__ void __launch_bounds__(256)
k_agg1(const float* __restrict__ W1, const float* __restrict__ b1,
       const float* __restrict__ W2, int n) {
    cudaGridDependencySynchronize();
    int warp = (blockIdx.x * blockDim.x + threadIdx.x) >> 5;
    int lane = threadIdx.x & 31;
    int half = lane >> 4;            // 0 or 1
    int hlane = lane & 15;
    int node = warp * 2 + half;
    if (node >= n) return;

    int deg = g_cnt[node * CNT_STRIDE]; if (deg > CAP) deg = CAP;
    int nq = (deg + 3) >> 2;         // int4 groups (sentinel-padded)
    const int4* list = reinterpret_cast<const int4*>(&g_bucket[node * CAP]);

    float4 acc = make_float4(0.f, 0.f, 0.f, 0.f);
    for (int q = hlane; q < nq; q += 16) {
        int4 s4 = __ldg(list + q);
        float4 v0 = __ldg(&g_xs4[s4.x]);
        float4 v1 = __ldg(&g_xs4[s4.y]);
        float4 v2 = __ldg(&g_xs4[s4.z]);
        float4 v3 = __ldg(&g_xs4[s4.w]);
        acc.x += (v0.x + v1.x) + (v2.x + v3.x);
        acc.y += (v0.y + v1.y) + (v2.y + v3.y);
        acc.z += (v0.z + v1.z) + (v2.z + v3.z);
        acc.w += (v0.w + v1.w) + (v2.w + v3.w);
    }
#pragma unroll
    for (int off = 8; off; off >>= 1) {
        acc.x += __shfl_xor_sync(0xffffffffu, acc.x, off);
        acc.y += __shfl_xor_sync(0xffffffffu, acc.y, off);
        acc.z += __shfl_xor_sync(0xffffffffu, acc.z, off);
        acc.w += __shfl_xor_sync(0xffffffffu, acc.w, off);
    }
    float dv = g_dinv[node];
    float4 self = __ldg(&g_xs4[node]);
    float4 a = make_float4((acc.x + self.x) * dv, (acc.y + self.y) * dv,
                           (acc.z + self.z) * dv, (acc.w + self.w) * dv);

    // MLP: the 16 lanes of each half-warp own the 16 hidden units of its node
    int j = hlane;
    float h = __ldg(&b1[j]);
    h = fmaf(a.x, __ldg(&W1[0 * F_HID + j]), h);
    h = fmaf(a.y, __ldg(&W1[1 * F_HID + j]), h);
    h = fmaf(a.z, __ldg(&W1[2 * F_HID + j]), h);
    h = fmaf(a.w, __ldg(&W1[3 * F_HID + j]), h);
    h = fmaxf(h, 0.0f);
    float p0 = h * __ldg(&W2[j * F_OUT + 0]);
    float p1 = h * __ldg(&W2[j * F_OUT + 1]);
#pragma unroll
    for (int off = 8; off; off >>= 1) {
        p0 += __shfl_xor_sync(0xffffffffu, p0, off);
        p1 += __shfl_xor_sync(0xffffffffu, p1, off);
    }
    if (hlane == 0) g_t2s[node] = make_float2(p0 * dv, p1 * dv);
}

// ---------------------------------------------------------------------------
// agg2 + bias: HALF-WARP per node, unguarded int4 gathers.
//   out = b2 + dinv * (Σ_nbrs t2s[s] + t2s[node])
// Self-zeros this node's counter for the next graph replay (last reader).
// PDL secondary: wait for agg1.
// ---------------------------------------------------------------------------
__global__ void __launch_bounds__(256)
k_agg2(const float* __restrict__ b2, float* __restrict__ out, int n) {
    cudaGridDependencySynchronize();
    int warp = (blockIdx.x * blockDim.x + threadIdx.x) >> 5;
    int lane = threadIdx.x & 31;
    int half = lane >> 4;
    int hlane = lane & 15;
    int node = warp * 2 + half;
    if (node >= n) return;

    int deg = g_cnt[node * CNT_STRIDE]; if (deg > CAP) deg = CAP;
    int nq = (deg + 3) >> 2;
    const int4* list = reinterpret_cast<const int4*>(&g_bucket[node * CAP]);

    float a0 = 0.f, a1 = 0.f;
    for (int q = hlane; q < nq; q += 16) {
        int4 s4 = __ldg(list + q);
        float2 v0 = __ldg(&g_t2s[s4.x]);
        float2 v1 = __ldg(&g_t2s[s4.y]);
        float2 v2 = __ldg(&g_t2s[s4.z]);
        float2 v3 = __ldg(&g_t2s[s4.w]);
        a0 += (v0.x + v1.x) + (v2.x + v3.x);
        a1 += (v0.y + v1.y) + (v2.y + v3.y);
    }
#pragma unroll
    for (int off = 8; off; off >>= 1) {
        a0 += __shfl_xor_sync(0xffffffffu, a0, off);
        a1 += __shfl_xor_sync(0xffffffffu, a1, off);
    }
    if (hlane == 0) {
        float dv = g_dinv[node];
        float2 self = g_t2s[node];
        float2 o;
        o.x = fmaf(dv, a0 + self.x, __ldg(&b2[0]));
        o.y = fmaf(dv, a1 + self.y, __ldg(&b2[1]));
        reinterpret_cast<float2*>(out)[node] = o;
        g_cnt[node * CNT_STRIDE] = 0;   // reset for next call (replaces memset node)
    }
}

// ---------------------------------------------------------------------------
// Launch — prep/agg1/agg2 use PDL (overlap launch with predecessor's drain);
// place stays fully stream-serialized (it conflicts with prior replay's agg2).
// ---------------------------------------------------------------------------
template <typename... Args>
static void launch_pdl(void (*kern)(Args...), int grid, int block, Args... args) {
    cudaLaunchConfig_t cfg = {};
    cfg.gridDim = dim3(grid);
    cfg.blockDim = dim3(block);
    cudaLaunchAttribute attr[1];
    attr[0].id = cudaLaunchAttributeProgrammaticStreamSerialization;
    attr[0].val.programmaticStreamSerializationAllowed = 1;
    cfg.attrs = attr;
    cfg.numAttrs = 1;
    cudaLaunchKernelEx(&cfg, kern, args...);
}

extern "C" void kernel_launch(void* const* d_in, const int* in_sizes, int n_in,
                              void* d_out, int out_size) {
    const float* x  = (const float*)d_in[0];
    const int*   ei = (const int*)d_in[1];   // int32 indices
    const float* W1 = (const float*)d_in[2];
    const float* b1 = (const float*)d_in[3];
    const float* W2 = (const float*)d_in[4];
    const float* b2 = (const float*)d_in[5];
    float* out = (float*)d_out;

    int N = in_sizes[0] / F_IN;
    int E = in_sizes[1] / 2;

    const int* src = ei;
    const int* dst = ei + E;

    const int T = 256;
    const int TP = 512;                       // place block size
    int nblk = (N + T - 1) / T;
    int e8 = (E + 7) / 8;
    int eblk = (e8 + TP - 1) / TP;
    int npairs = (N + 1) / 2;                 // two nodes per warp
    int wblk = (npairs + 7) / 8;              // 8 warps per CTA

    k_place<<<eblk, TP>>>(src, dst, E);
    launch_pdl(k_prep, nblk, T, x, N);
    launch_pdl(k_agg1, wblk, T, W1, b1, W2, N);
    launch_pdl(k_agg2, wblk, T, b2, out, N);
}

// round 17
// speedup vs baseline: 1.0156x; 1.0002x over previous
#include <cuda_runtime.h>
#include <cuda_bf16.h>
#include <cstdint>

#define MAX_NODES 100000
#define CAP 192          // max in-degree slots (Poisson(64): P(>=192) < 1e-40)
#define CNT_STRIDE 8     // one counter per 32B sector (proven best)
#define F_IN 4
#define F_HID 16
#define F_OUT 2

// Scratch (__device__ globals; no runtime allocation).
// g_cnt starts zero (bss) and is re-zeroed by k_agg2 every call — no memset needed.
__device__ int    g_cnt[MAX_NODES * CNT_STRIDE];         // padded in-degree counters
__device__ __align__(16) int g_bucket[MAX_NODES * CAP];  // per-dst src lists
__device__ float  g_dinv[MAX_NODES];
__device__ __align__(16) float4 g_xs4[MAX_NODES + 1];    // x * dinv; [N] = 0 sentinel
__device__ __align__(8)  float2 g_t2s[MAX_NODES + 1];    // t2 * dinv; [N] = 0 sentinel

// ---------------------------------------------------------------------------
// placement: build per-dst src lists; padded counter doubles as degree.
// 8 edges/thread. NO PDL on this kernel (races with prior replay's agg2 reset).
// ---------------------------------------------------------------------------
__global__ void __launch_bounds__(512)
k_place(const int* __restrict__ src, const int* __restrict__ dst, int E) {
    int e0 = (blockIdx.x * blockDim.x + threadIdx.x) * 8;
    if (e0 + 7 < E) {
        int4 sa = *reinterpret_cast<const int4*>(src + e0);
        int4 sb = *reinterpret_cast<const int4*>(src + e0 + 4);
        int4 da = *reinterpret_cast<const int4*>(dst + e0);
        int4 db = *reinterpret_cast<const int4*>(dst + e0 + 4);
        int p;
        p = atomicAdd(&g_cnt[da.x * CNT_STRIDE], 1); if (p < CAP) g_bucket[da.x * CAP + p] = sa.x;
        p = atomicAdd(&g_cnt[da.y * CNT_STRIDE], 1); if (p < CAP) g_bucket[da.y * CAP + p] = sa.y;
        p = atomicAdd(&g_cnt[da.z * CNT_STRIDE], 1); if (p < CAP) g_bucket[da.z * CAP + p] = sa.z;
        p = atomicAdd(&g_cnt[da.w * CNT_STRIDE], 1); if (p < CAP) g_bucket[da.w * CAP + p] = sa.w;
        p = atomicAdd(&g_cnt[db.x * CNT_STRIDE], 1); if (p < CAP) g_bucket[db.x * CAP + p] = sb.x;
        p = atomicAdd(&g_cnt[db.y * CNT_STRIDE], 1); if (p < CAP) g_bucket[db.y * CAP + p] = sb.y;
        p = atomicAdd(&g_cnt[db.z * CNT_STRIDE], 1); if (p < CAP) g_bucket[db.z * CAP + p] = sb.z;
        p = atomicAdd(&g_cnt[db.w * CNT_STRIDE], 1); if (p < CAP) g_bucket[db.w * CAP + p] = sb.w;
    } else {
        for (int e = e0; e < E; e++) {
            int s = src[e], d = dst[e];
            int p = atomicAdd(&g_cnt[d * CNT_STRIDE], 1);
            if (p < CAP) g_bucket[d * CAP + p] = s;
        }
    }
}

// ---------------------------------------------------------------------------
// prep: deg = cnt + 1 (self loop); dinv = rsqrt(deg); xs = x * dinv;
// pad bucket row to multiple of 4 with sentinel index n (zero row).
// PDL secondary: wait for place before reading g_cnt/g_bucket.
// ---------------------------------------------------------------------------
__global__ void k_prep(const float* __restrict__ x, int n) {
    cudaGridDependencySynchronize();
    int i = blockIdx.x * blockDim.x + threadIdx.x;
    if (i == 0) {
        g_xs4[n] = make_float4(0.f, 0.f, 0.f, 0.f);
        g_t2s[n] = make_float2(0.f, 0.f);
    }
    if (i >= n) return;
    int cnt = g_cnt[i * CNT_STRIDE]; if (cnt > CAP) cnt = CAP;
    // sentinel-pad to multiple of 4 so agg gathers need no tail guards
    int padded = (cnt + 3) & ~3;
    for (int k = cnt; k < padded; k++) g_bucket[i * CAP + k] = n;

    float dv = rsqrtf((float)(cnt + 1));
    g_dinv[i] = dv;
    float4 xv = reinterpret_cast<const float4*>(x)[i];
    g_xs4[i] = make_float4(xv.x * dv, xv.y * dv, xv.z * dv, xv.w * dv);
}

// ---------------------------------------------------------------------------
// agg1 + dense: HALF-WARP per node (two nodes per warp), unguarded int4 gathers.
//   a = dinv * (Σ_nbrs xs[s] + xs[node]);  h = relu(a@W1+b1);  t2s = (h@W2)*dinv
// PDL secondary: wait for prep.
// ---------------------------------------------------------------------------
__global__ void __launch_bounds__(256)
k_agg1(const float* __restrict__ W1, const float* __restrict__ b1,
       const float* __restrict__ W2, int n) {
    cudaGridDependencySynchronize();
    int warp = (blockIdx.x * blockDim.x + threadIdx.x) >> 5;
    int lane = threadIdx.x & 31;
    int half = lane >> 4;            // 0 or 1
    int hlane = lane & 15;
    int node = warp * 2 + half;
    if (node >= n) return;

    int deg = g_cnt[node * CNT_STRIDE]; if (deg > CAP) deg = CAP;
    int nq = (deg + 3) >> 2;         // int4 groups (sentinel-padded)
    const int4* list = reinterpret_cast<const int4*>(&g_bucket[node * CAP]);

    float4 acc = make_float4(0.f, 0.f, 0.f, 0.f);
    for (int q = hlane; q < nq; q += 16) {
        int4 s4 = __ldg(list + q);
        float4 v0 = __ldg(&g_xs4[s4.x]);
        float4 v1 = __ldg(&g_xs4[s4.y]);
        float4 v2 = __ldg(&g_xs4[s4.z]);
        float4 v3 = __ldg(&g_xs4[s4.w]);
        acc.x += (v0.x + v1.x) + (v2.x + v3.x);
        acc.y += (v0.y + v1.y) + (v2.y + v3.y);
        acc.z += (v0.z + v1.z) + (v2.z + v3.z);
        acc.w += (v0.w + v1.w) + (v2.w + v3.w);
    }
#pragma unroll
    for (int off = 8; off; off >>= 1) {
        acc.x += __shfl_xor_sync(0xffffffffu, acc.x, off);
        acc.y += __shfl_xor_sync(0xffffffffu, acc.y, off);
        acc.z += __shfl_xor_sync(0xffffffffu, acc.z, off);
        acc.w += __shfl_xor_sync(0xffffffffu, acc.w, off);
    }
    float dv = g_dinv[node];
    float4 self = __ldg(&g_xs4[node]);
    float4 a = make_float4((acc.x + self.x) * dv, (acc.y + self.y) * dv,
                           (acc.z + self.z) * dv, (acc.w + self.w) * dv);

    // MLP: the 16 lanes of each half-warp own the 16 hidden units of its node
    int j = hlane;
    float h = __ldg(&b1[j]);
    h = fmaf(a.x, __ldg(&W1[0 * F_HID + j]), h);
    h = fmaf(a.y, __ldg(&W1[1 * F_HID + j]), h);
    h = fmaf(a.z, __ldg(&W1[2 * F_HID + j]), h);
    h = fmaf(a.w, __ldg(&W1[3 * F_HID + j]), h);
    h = fmaxf(h, 0.0f);
    float p0 = h * __ldg(&W2[j * F_OUT + 0]);
    float p1 = h * __ldg(&W2[j * F_OUT + 1]);
#pragma unroll
    for (int off = 8; off; off >>= 1) {
        p0 += __shfl_xor_sync(0xffffffffu, p0, off);
        p1 += __shfl_xor_sync(0xffffffffu, p1, off);
    }
    if (hlane == 0) g_t2s[node] = make_float2(p0 * dv, p1 * dv);
}

// ---------------------------------------------------------------------------
// agg2 + bias: HALF-WARP per node, unguarded int4 gathers.
//   out = b2 + dinv * (Σ_nbrs t2s[s] + t2s[node])
// Self-zeros this node's counter for the next graph replay (last reader).
// PDL secondary: wait for agg1.
// ---------------------------------------------------------------------------
__global__ void __launch_bounds__(256)
k_agg2(const float* __restrict__ b2, float* __restrict__ out, int n) {
    cudaGridDependencySynchronize();
    int warp = (blockIdx.x * blockDim.x + threadIdx.x) >> 5;
    int lane = threadIdx.x & 31;
    int half = lane >> 4;
    int hlane = lane & 15;
    int node = warp * 2 + half;
    if (node >= n) return;

    int deg = g_cnt[node * CNT_STRIDE]; if (deg > CAP) deg = CAP;
    int nq = (deg + 3) >> 2;
    const int4* list = reinterpret_cast<const int4*>(&g_bucket[node * CAP]);

    float a0 = 0.f, a1 = 0.f;
    for (int q = hlane; q < nq; q += 16) {
        int4 s4 = __ldg(list + q);
        float2 v0 = __ldg(&g_t2s[s4.x]);
        float2 v1 = __ldg(&g_t2s[s4.y]);
        float2 v2 = __ldg(&g_t2s[s4.z]);
        float2 v3 = __ldg(&g_t2s[s4.w]);
        a0 += (v0.x + v1.x) + (v2.x + v3.x);
        a1 += (v0.y + v1.y) + (v2.y + v3.y);
    }
#pragma unroll
    for (int off = 8; off; off >>= 1) {
        a0 += __shfl_xor_sync(0xffffffffu, a0, off);
        a1 += __shfl_xor_sync(0xffffffffu, a1, off);
    }
    if (hlane == 0) {
        float dv = g_dinv[node];
        float2 self = g_t2s[node];
        float2 o;
        o.x = fmaf(dv, a0 + self.x, __ldg(&b2[0]));
        o.y = fmaf(dv, a1 + self.y, __ldg(&b2[1]));
        reinterpret_cast<float2*>(out)[node] = o;
        g_cnt[node * CNT_STRIDE] = 0;   // reset for next call (replaces memset node)
    }
}

// ---------------------------------------------------------------------------
// Launch — prep/agg1/agg2 use PDL (overlap launch with predecessor's drain);
// place stays fully stream-serialized (it conflicts with prior replay's agg2).
// ---------------------------------------------------------------------------
template <typename... Args>
static void launch_pdl(void (*kern)(Args...), int grid, int block, Args... args) {
    cudaLaunchConfig_t cfg = {};
    cfg.gridDim = dim3(grid);
    cfg.blockDim = dim3(block);
    cudaLaunchAttribute attr[1];
    attr[0].id = cudaLaunchAttributeProgrammaticStreamSerialization;
    attr[0].val.programmaticStreamSerializationAllowed = 1;
    cfg.attrs = attr;
    cfg.numAttrs = 1;
    cudaLaunchKernelEx(&cfg, kern, args...);
}

extern "C" void kernel_launch(void* const* d_in, const int* in_sizes, int n_in,
                              void* d_out, int out_size) {
    const float* x  = (const float*)d_in[0];
    const int*   ei = (const int*)d_in[1];   // int32 indices
    const float* W1 = (const float*)d_in[2];
    const float* b1 = (const float*)d_in[3];
    const float* W2 = (const float*)d_in[4];
    const float* b2 = (const float*)d_in[5];
    float* out = (float*)d_out;

    int N = in_sizes[0] / F_IN;
    int E = in_sizes[1] / 2;

    const int* src = ei;
    const int* dst = ei + E;

    const int T = 256;
    const int TP = 512;                       // place block size
    int nblk = (N + T - 1) / T;
    int e8 = (E + 7) / 8;
    int eblk = (e8 + TP - 1) / TP;
    int npairs = (N + 1) / 2;                 // two nodes per warp
    int wblk = (npairs + 7) / 8;              // 8 warps per CTA

    k_place<<<eblk, TP>>>(src, dst, E);
    launch_pdl(k_prep, nblk, T, x, N);
    launch_pdl(k_agg1, wblk, T, W1, b1, W2, N);
    launch_pdl(k_agg2, wblk, T, b2, out, N);
}